// round 15
// baseline (speedup 1.0000x reference)
#include <cuda_runtime.h>
#include <cuda_bf16.h>
#include <cuda_fp16.h>
#include <mma.h>
#include <math.h>
#include <stdint.h>

using namespace nvcuda;

// Problem constants
#define BS 4
#define SEQ 2048
#define DIM 1024
#define NH 16
#define DK 64
#define MTOT (BS * SEQ)
#define FNEG (-1e30f)

// ---------------------------------------------------------------------------
// Scratch (device globals). fp16 single-plane activations + weights.
// ---------------------------------------------------------------------------
__device__ __half g_Qr[(size_t)MTOT * DIM];
__device__ __half g_Kr[(size_t)MTOT * DIM];
__device__ __half g_Vr[(size_t)MTOT * DIM];
__device__ __half g_Qp[(size_t)MTOT * DIM];
__device__ __half g_Kp[(size_t)MTOT * DIM];
__device__ __half g_Vp[(size_t)MTOT * DIM];
__device__ __half g_Cc[(size_t)MTOT * DIM];
__device__ __half g_W[(size_t)4 * DIM * DIM];
__device__ float g_bqkv[3 * DIM];
__device__ int g_vidx[BS * SEQ];
__device__ int g_pidx[BS * SEQ];
__device__ int g_nvalid[BS];

// ---------------------------------------------------------------------------
// Mask compaction: one block per batch, prefix sum over 2048 mask ints.
// ---------------------------------------------------------------------------
__global__ __launch_bounds__(256) void compact_mask(const int* __restrict__ mask)
{
    __shared__ int part[256];
    const int b = blockIdx.x, t = threadIdx.x;
    int loc[8], sum = 0;
#pragma unroll
    for (int i = 0; i < 8; i++) {
        loc[i] = (mask[b * SEQ + t * 8 + i] != 0) ? 1 : 0;
        sum += loc[i];
    }
    part[t] = sum;
    __syncthreads();
    for (int off = 1; off < 256; off <<= 1) {
        int v = (t >= off) ? part[t - off] : 0;
        __syncthreads();
        part[t] += v;
        __syncthreads();
    }
    int pre = part[t] - sum;
#pragma unroll
    for (int i = 0; i < 8; i++) {
        int s = t * 8 + i;
        g_pidx[b * SEQ + s] = pre;
        if (loc[i]) { g_vidx[b * SEQ + pre] = s; pre++; }
    }
    if (t == 255) g_nvalid[b] = part[255];
}

// ---------------------------------------------------------------------------
// Gather raw q/k/v rows into compacted single-fp16 planes (zero pad).
// ---------------------------------------------------------------------------
__global__ __launch_bounds__(256) void gather_qkv(
    const float* __restrict__ q, const float* __restrict__ k,
    const float* __restrict__ v)
{
    const int b = blockIdx.y, i = blockIdx.x, t = threadIdx.x;
    const int nv = g_nvalid[b];
    const size_t dst = ((size_t)b * SEQ + i) * DIM + t * 4;
    if (i < nv) {
        const int s = g_vidx[b * SEQ + i];
        const size_t src = ((size_t)b * SEQ + s) * DIM + t * 4;
        float4 a = *(const float4*)(q + src);
        float4 c = *(const float4*)(k + src);
        float4 d = *(const float4*)(v + src);
        *(__half2*)(g_Qr + dst)     = __floats2half2_rn(a.x, a.y);
        *(__half2*)(g_Qr + dst + 2) = __floats2half2_rn(a.z, a.w);
        *(__half2*)(g_Kr + dst)     = __floats2half2_rn(c.x, c.y);
        *(__half2*)(g_Kr + dst + 2) = __floats2half2_rn(c.z, c.w);
        *(__half2*)(g_Vr + dst)     = __floats2half2_rn(d.x, d.y);
        *(__half2*)(g_Vr + dst + 2) = __floats2half2_rn(d.z, d.w);
    } else {
        const __half2 z = __floats2half2_rn(0.f, 0.f);
        *(__half2*)(g_Qr + dst) = z; *(__half2*)(g_Qr + dst + 2) = z;
        *(__half2*)(g_Kr + dst) = z; *(__half2*)(g_Kr + dst + 2) = z;
        *(__half2*)(g_Vr + dst) = z; *(__half2*)(g_Vr + dst + 2) = z;
    }
}

// ---------------------------------------------------------------------------
// Convert weights to fp16 (Wq pre-scaled 0.125) + bias prep (merged kernel).
// ---------------------------------------------------------------------------
__global__ __launch_bounds__(256) void prep_weights(
    const float* __restrict__ Wq, const float* __restrict__ Wk,
    const float* __restrict__ Wv, const float* __restrict__ Wo,
    const float* __restrict__ bq, const float* __restrict__ bk,
    const float* __restrict__ bv)
{
    const int mat = blockIdx.y;
    const int bx = blockIdx.x;
    const int t = threadIdx.x;
    const float* src = (mat == 0) ? Wq : (mat == 1) ? Wk : (mat == 2) ? Wv : Wo;
    const float sc = (mat == 0) ? 0.125f : 1.0f;
    const size_t idx = (size_t)bx * 1024 + t * 4;
    float4 a = *(const float4*)(src + idx);
    const size_t dst = (size_t)mat * DIM * DIM + idx;
    *(__half2*)(g_W + dst)     = __floats2half2_rn(a.x * sc, a.y * sc);
    *(__half2*)(g_W + dst + 2) = __floats2half2_rn(a.z * sc, a.w * sc);
    // bias prep piggybacked on the first three x-blocks of mat 0
    if (mat == 0 && bx < 3) {
        const float* bsrc = (bx == 0) ? bq : (bx == 1) ? bk : bv;
        const float sc2 = (bx == 0) ? 0.125f : 1.0f;
#pragma unroll
        for (int j = 0; j < 4; j++) {
            const int i = t * 4 + j;
            g_bqkv[bx * 1024 + i] = bsrc[i] * sc2;
        }
    }
}

// ---------------------------------------------------------------------------
// Fill masked output rows with bias bo.
// ---------------------------------------------------------------------------
__global__ __launch_bounds__(256) void fill_masked(
    const int* __restrict__ mask, const float* __restrict__ bo,
    float* __restrict__ out)
{
    const int b = blockIdx.y, s = blockIdx.x, t = threadIdx.x;
    if (mask[b * SEQ + s] != 0) return;
    const size_t dst = ((size_t)b * SEQ + s) * DIM;
    ((float4*)(out + dst))[t] = ((const float4*)bo)[t];
}

// ---------------------------------------------------------------------------
// GEMM core (NT): C[128,128] = A[128,K] @ W[128,K]^T + bias, fp16.
// BK=64 (16 iters), cp.async 2-stage, 2 CTAs/SM. 256 threads, 8 warps (2x4),
// warp tile 64x32.
// MODE 0: fp16 plane out (QKV). MODE 1: fp32 scatter-to-output via vidx (O).
// ---------------------------------------------------------------------------
#define GBM 128
#define GBN 128
#define GBK 64
#define GSTR 72                  // smem row stride in halfs (144B)
#define PLANE_B 18432            // 128*72*2 bytes
#define STAGE_B (2 * PLANE_B)    // A, W
#define GEMM_SMEM 73728          // 2 stages (epilogue 67584 fits inside)

template<int MODE>
__device__ __forceinline__ void gemm_core(
    const __half* __restrict__ Ap, const __half* __restrict__ Bp,
    const float* __restrict__ biasp,
    __half* __restrict__ Hp,
    float* __restrict__ outb, const int* __restrict__ vl, int nrem)
{
    extern __shared__ char smem[];
    const uint32_t sb = (uint32_t)__cvta_generic_to_shared(smem);
    const int tid = threadIdx.x;
    const int w = tid >> 5, wr = w >> 2, wc = w & 3;

    const __half* gsrc[2] = { Ap, Bp };

    wmma::fragment<wmma::accumulator, 16, 16, 16, float> acc[4][2];
#pragma unroll
    for (int i = 0; i < 4; i++)
#pragma unroll
        for (int j = 0; j < 2; j++) wmma::fill_fragment(acc[i][j], 0.f);

    // 2048 16B chunks per stage (2 planes x 1024), 8 per thread
    auto issue = [&](int t, int buf) {
#pragma unroll
        for (int p = 0; p < 8; p++) {
            const int idx = p * 256 + tid;            // 0..2047
            const int plane = idx >> 10;
            const int c = idx & 1023;
            const int row = c >> 3, col = (c & 7) * 8;
            const void* src = gsrc[plane] + (size_t)row * DIM + t * GBK + col;
            const uint32_t dst = sb + buf * STAGE_B + plane * PLANE_B
                               + (row * GSTR + col) * 2;
            asm volatile("cp.async.cg.shared.global [%0], [%1], 16;\n"
                         :: "r"(dst), "l"(src));
        }
        asm volatile("cp.async.commit_group;\n");
    };

    auto compute = [&](int buf) {
        const __half* As = (const __half*)(smem + buf * STAGE_B);
        const __half* Bs = As + PLANE_B / 2;
#pragma unroll
        for (int kk = 0; kk < 4; kk++) {
            wmma::fragment<wmma::matrix_a, 16, 16, 16, __half, wmma::row_major> af[4];
#pragma unroll
            for (int i = 0; i < 4; i++)
                wmma::load_matrix_sync(af[i], As + (wr * 64 + i * 16) * GSTR + kk * 16, GSTR);
#pragma unroll
            for (int j = 0; j < 2; j++) {
                wmma::fragment<wmma::matrix_b, 16, 16, 16, __half, wmma::col_major> bf;
                wmma::load_matrix_sync(bf, Bs + (wc * 32 + j * 16) * GSTR + kk * 16, GSTR);
#pragma unroll
                for (int i = 0; i < 4; i++)
                    wmma::mma_sync(acc[i][j], af[i], bf, acc[i][j]);
            }
        }
    };

    const int NT = DIM / GBK;   // 16
    issue(0, 0);
    for (int t = 0; t < NT; t++) {
        if (t + 1 < NT) {
            issue(t + 1, (t + 1) & 1);
            asm volatile("cp.async.wait_group 1;\n");
        } else {
            asm volatile("cp.async.wait_group 0;\n");
        }
        __syncthreads();
        compute(t & 1);
        __syncthreads();
    }

    // epilogue: fp32 staging + bias
    float* Cs = (float*)smem;   // 128 x 132
#pragma unroll
    for (int i = 0; i < 4; i++)
#pragma unroll
        for (int j = 0; j < 2; j++)
            wmma::store_matrix_sync(Cs + (wr * 64 + i * 16) * 132 + wc * 32 + j * 16,
                                    acc[i][j], 132, wmma::mem_row_major);
    __syncthreads();

#pragma unroll
    for (int it = 0; it < 16; it++) {
        const int f = tid + it * 256;
        const int r = f >> 5, c = (f & 31) * 4;
        float4 vv = *(const float4*)(Cs + r * 132 + c);
        const float4 bb = *(const float4*)(biasp + c);
        const float x0 = vv.x + bb.x;
        const float x1 = vv.y + bb.y;
        const float x2 = vv.z + bb.z;
        const float x3 = vv.w + bb.w;
        if (MODE == 0) {
            const size_t off = (size_t)r * DIM + c;
            *(__half2*)(Hp + off)     = __floats2half2_rn(x0, x1);
            *(__half2*)(Hp + off + 2) = __floats2half2_rn(x2, x3);
        } else {
            if (r < nrem) {   // valid compacted row -> scatter to original slot
                const int orow = vl[r];
                *(float4*)(outb + (size_t)orow * DIM + c) =
                    make_float4(x0, x1, x2, x3);
            }
        }
    }
}

// fused QKV projection: grid (3072/128, MTOT/128)
__global__ __launch_bounds__(256, 2) void gemm_qkv()
{
    const int m0 = blockIdx.y * GBM;
    const int n0 = blockIdx.x * GBN;
    {
        const int nv = g_nvalid[m0 >> 11];
        const int nvpad = (nv + GBM - 1) & ~(GBM - 1);
        if ((m0 & (SEQ - 1)) >= nvpad) return;
    }
    const int sec = n0 >> 10;          // 0=Q, 1=K, 2=V
    const int nc = n0 & 1023;
    const __half* Ap = (sec == 0) ? g_Qr : (sec == 1) ? g_Kr : g_Vr;
    __half* Hp = ((sec == 0) ? g_Qp : (sec == 1) ? g_Kp : g_Vp)
                 + (size_t)m0 * DIM + nc;
    gemm_core<0>(Ap + (size_t)m0 * DIM, g_W + (size_t)n0 * DIM,
                 g_bqkv + n0, Hp, nullptr, nullptr, 0);
}

// output projection with scattered epilogue: grid (1024/128, MTOT/128)
__global__ __launch_bounds__(256, 2) void gemm_o(const float* __restrict__ bo,
                                                 float* __restrict__ out)
{
    const int m0 = blockIdx.y * GBM;
    const int n0 = blockIdx.x * GBN;
    const int b  = m0 >> 11;
    const int ml = m0 & (SEQ - 1);
    const int nv = g_nvalid[b];
    {
        const int nvpad = (nv + GBM - 1) & ~(GBM - 1);
        if (ml >= nvpad) return;
    }
    gemm_core<1>(g_Cc + (size_t)m0 * DIM,
                 g_W + (size_t)3 * DIM * DIM + (size_t)n0 * DIM,
                 bo + n0, nullptr,
                 out + (size_t)b * SEQ * DIM + n0,
                 g_vidx + b * SEQ + ml, nv - ml);
}

// ---------------------------------------------------------------------------
// Flash attention, SOFTWARE-PIPELINED: S-MMA shifted one iteration ahead.
// Per iter: [softmax(S[i]) -> P[i]] sync [S[i+1]-MMA || PV[i]-MMA] sync.
// 2 syncs/iter (was 4); both MMAs issue back-to-back. K,V double-buffered;
// one cp.async group {V[i+1], K[i+2]} per iter (always committed).
// smem (bytes): Q 0 (18432) | K s: 18432+s*9216 | V s: 36864+s*9216
//               S f32 55296 (128x72, 36864) | P fp16 92160 (18432)
//               total 110592 -> 2 CTAs/SM
// ---------------------------------------------------------------------------
#define ABQ 128
#define ABK 64
#define APB 72
#define APS 72
#define FQOF 0
#define FKOF(s) (18432 + (s) * 9216)
#define FVOF(s) (36864 + (s) * 9216)
#define FSOF 55296
#define FPOF 92160
#define FA_SMEM 110592

__global__ __launch_bounds__(256, 2) void flash_attn_fp16()
{
    const int b = blockIdx.z, h = blockIdx.y;
    const int nk = g_nvalid[b];
    const int q0 = blockIdx.x * ABQ;
    if (q0 >= nk) return;

    extern __shared__ char smem[];
    const uint32_t sb = (uint32_t)__cvta_generic_to_shared(smem);
    __half* Qs  = (__half*)(smem + FQOF);
    float*  Ssm = (float*)(smem + FSOF);
    __half* Ps  = (__half*)(smem + FPOF);

    const int tid = threadIdx.x;
    const int w = tid >> 5;
    const int niter = (nk + ABK - 1) / ABK;

    // one K or V chunk = 64 rows x 64 halfs = 512 16B chunks -> 2 per thread
    auto issueK = [&](int i) {   // K[i] -> Kbuf[i&1]
        const size_t rb = ((size_t)b * SEQ + i * ABK) * DIM + h * DK;
#pragma unroll
        for (int p = 0; p < 2; p++) {
            const int c = p * 256 + tid;
            const int row = c >> 3, col = (c & 7) * 8;
            const void* src = g_Kp + rb + (size_t)row * DIM + col;
            const uint32_t dst = sb + FKOF(i & 1) + (row * APB + col) * 2;
            asm volatile("cp.async.cg.shared.global [%0], [%1], 16;\n"
                         :: "r"(dst), "l"(src));
        }
    };
    auto issueV = [&](int i) {   // V[i] -> Vbuf[i&1]
        const size_t rb = ((size_t)b * SEQ + i * ABK) * DIM + h * DK;
#pragma unroll
        for (int p = 0; p < 2; p++) {
            const int c = p * 256 + tid;
            const int row = c >> 3, col = (c & 7) * 8;
            const void* src = g_Vp + rb + (size_t)row * DIM + col;
            const uint32_t dst = sb + FVOF(i & 1) + (row * APB + col) * 2;
            asm volatile("cp.async.cg.shared.global [%0], [%1], 16;\n"
                         :: "r"(dst), "l"(src));
        }
    };
    // group {V[i], K[i+1]}; always commits (possibly empty) for uniform counting
    auto issueKV = [&](int i) {
        if (i < niter) issueV(i);
        if (i + 1 < niter) issueK(i + 1);
        asm volatile("cp.async.commit_group;\n");
    };

    auto smma = [&](int i) {     // S = Q @ K[i]^T -> Ssm
        const __half* Ks = (const __half*)(smem + FKOF(i & 1));
        wmma::fragment<wmma::accumulator, 16, 16, 16, float> acc[4];
#pragma unroll
        for (int j = 0; j < 4; j++) wmma::fill_fragment(acc[j], 0.f);
#pragma unroll
        for (int kk = 0; kk < 4; kk++) {
            wmma::fragment<wmma::matrix_a, 16, 16, 16, __half, wmma::row_major> af;
            wmma::load_matrix_sync(af, Qs + (16 * w) * APB + kk * 16, APB);
#pragma unroll
            for (int j = 0; j < 4; j++) {
                wmma::fragment<wmma::matrix_b, 16, 16, 16, __half, wmma::col_major> bf;
                wmma::load_matrix_sync(bf, Ks + (j * 16) * APB + kk * 16, APB);
                wmma::mma_sync(acc[j], af, bf, acc[j]);
            }
        }
#pragma unroll
        for (int j = 0; j < 4; j++)
            wmma::store_matrix_sync(Ssm + (16 * w) * APS + j * 16, acc[j], APS,
                                    wmma::mem_row_major);
    };

    // ---- prologue ----
    issueK(0);
    asm volatile("cp.async.commit_group;\n");     // G0 = {K0}
    {   // Q tile: 128 rows x 64 halfs
        const size_t rb = ((size_t)b * SEQ + q0) * DIM + h * DK;
        for (int f = tid; f < 1024; f += 256) {
            const int r = f >> 3, c = (f & 7) * 8;
            *(uint4*)(Qs + r * APB + c) = *(const uint4*)(g_Qp + rb + (size_t)r * DIM + c);
        }
    }
    issueKV(0);                                   // G1 = {V0, K1?}
    asm volatile("cp.async.wait_group 1;\n");     // K0 arrived (G1 pending)
    __syncthreads();                              // Q + K0 visible
    smma(0);
    __syncthreads();                              // S0 visible

    wmma::fragment<wmma::accumulator, 16, 16, 16, float> accO[4];
#pragma unroll
    for (int j = 0; j < 4; j++) wmma::fill_fragment(accO[j], 0.f);

    const int row = tid >> 1;
    const int cbase = (tid & 1) * 32;
    float lrun = 0.f;

    // ---- pipelined mainloop ----
    for (int i = 0; i < niter; i++) {
        const int kt = i * ABK;

        // softmax on S[i]: p = exp(s), pad -> 0 exactly; write P[i]
        float lsum = 0.f;
#pragma unroll
        for (int c = 0; c < 32; c += 2) {
            float s0 = Ssm[row * APS + cbase + c];
            float s1 = Ssm[row * APS + cbase + c + 1];
            if (kt + cbase + c >= nk)     s0 = FNEG;
            if (kt + cbase + c + 1 >= nk) s1 = FNEG;
            const float p0 = __expf(s0), p1 = __expf(s1);
            lsum += p0 + p1;
            *(__half2*)(Ps + row * APB + cbase + c) = __floats2half2_rn(p0, p1);
        }
        lrun += lsum + __shfl_xor_sync(0xffffffffu, lsum, 1);

        asm volatile("cp.async.wait_group 0;\n"); // V[i] (+K[i+1]) arrived
        __syncthreads();                          // P[i] visible, S free, K/V visible

        if (i + 1 < niter) issueKV(i + 1);        // launch {V[i+1], K[i+2]?}

        // packed MMA phase: S[i+1] and PV[i] issue together
        if (i + 1 < niter) smma(i + 1);
        {
            const __half* Vs = (const __half*)(smem + FVOF(i & 1));
#pragma unroll
            for (int kk = 0; kk < 4; kk++) {
                wmma::fragment<wmma::matrix_a, 16, 16, 16, __half, wmma::row_major> pf;
                wmma::load_matrix_sync(pf, Ps + (16 * w) * APB + kk * 16, APB);
#pragma unroll
                for (int j = 0; j < 4; j++) {
                    wmma::fragment<wmma::matrix_b, 16, 16, 16, __half, wmma::row_major> vf;
                    wmma::load_matrix_sync(vf, Vs + (kk * 16) * APB + j * 16, APB);
                    wmma::mma_sync(accO[j], pf, vf, accO[j]);
                }
            }
        }
        __syncthreads();                          // S[i+1] visible; K/V/P reads sealed
    }

    // ---- epilogue: stage O through S region, normalize, emit fp16 context ----
    float* Osm = (float*)(smem + FSOF);
#pragma unroll
    for (int j = 0; j < 4; j++)
        wmma::store_matrix_sync(Osm + (16 * w) * 68 + j * 16, accO[j], 68,
                                wmma::mem_row_major);
    __syncthreads();

    const float inv = (lrun > 0.f) ? (1.f / lrun) : 0.f;
    const size_t ob = ((size_t)b * SEQ + q0 + row) * DIM + h * DK + cbase;
#pragma unroll
    for (int c = 0; c < 32; c += 2) {
        const float a = Osm[row * 68 + cbase + c] * inv;
        const float d = Osm[row * 68 + cbase + c + 1] * inv;
        *(__half2*)(g_Cc + ob + c) = __floats2half2_rn(a, d);
    }
}

// ---------------------------------------------------------------------------
// launch
// ---------------------------------------------------------------------------
extern "C" void kernel_launch(void* const* d_in, const int* in_sizes, int n_in,
                              void* d_out, int out_size)
{
    const float* q    = (const float*)d_in[0];
    const float* k    = (const float*)d_in[1];
    const float* v    = (const float*)d_in[2];
    const int*   mask = (const int*)  d_in[3];
    const float* Wq   = (const float*)d_in[4];
    const float* bq   = (const float*)d_in[5];
    const float* Wk   = (const float*)d_in[6];
    const float* bk   = (const float*)d_in[7];
    const float* Wv   = (const float*)d_in[8];
    const float* bv   = (const float*)d_in[9];
    const float* Wo   = (const float*)d_in[10];
    const float* bo   = (const float*)d_in[11];
    float* out = (float*)d_out;

    cudaFuncSetAttribute(gemm_qkv, cudaFuncAttributeMaxDynamicSharedMemorySize, GEMM_SMEM);
    cudaFuncSetAttribute(gemm_o,   cudaFuncAttributeMaxDynamicSharedMemorySize, GEMM_SMEM);
    cudaFuncSetAttribute(flash_attn_fp16, cudaFuncAttributeMaxDynamicSharedMemorySize, FA_SMEM);

    // 1. compact mask, build indices
    compact_mask<<<BS, 256>>>(mask);

    // 2. gather raw q/k/v (fp16); convert weights + bias (merged)
    gather_qkv<<<dim3(SEQ, BS), 256>>>(q, k, v);
    prep_weights<<<dim3(1024, 4), 256>>>(Wq, Wk, Wv, Wo, bq, bk, bv);

    // 3. fused QKV projection (fp16; scale folded into Wq/bq)
    gemm_qkv<<<dim3(3 * DIM / GBN, MTOT / GBM), 256, GEMM_SMEM>>>();

    // 4. flash attention (software-pipelined, single-pass fp16)
    flash_attn_fp16<<<dim3(SEQ / ABQ, NH, BS), 256, FA_SMEM>>>();

    // 5. output projection, epilogue scatters valid rows directly to out
    gemm_o<<<dim3(DIM / GBN, MTOT / GBM), 256, GEMM_SMEM>>>(bo, out);

    // 6. masked rows = bo
    fill_masked<<<dim3(SEQ, BS), 256>>>(mask, bo, out);
}

// round 16
// speedup vs baseline: 1.0129x; 1.0129x over previous
#include <cuda_runtime.h>
#include <cuda_bf16.h>
#include <cuda_fp16.h>
#include <mma.h>
#include <math.h>
#include <stdint.h>

using namespace nvcuda;

// Problem constants
#define BS 4
#define SEQ 2048
#define DIM 1024
#define NH 16
#define DK 64
#define MTOT (BS * SEQ)
#define FNEG (-1e30f)

// ---------------------------------------------------------------------------
// Scratch (device globals). fp16 single-plane activations + weights.
// ---------------------------------------------------------------------------
__device__ __half g_Qr[(size_t)MTOT * DIM];
__device__ __half g_Kr[(size_t)MTOT * DIM];
__device__ __half g_Vr[(size_t)MTOT * DIM];
__device__ __half g_Qp[(size_t)MTOT * DIM];
__device__ __half g_Kp[(size_t)MTOT * DIM];
__device__ __half g_Vp[(size_t)MTOT * DIM];
__device__ __half g_Cc[(size_t)MTOT * DIM];
__device__ __half g_W[(size_t)4 * DIM * DIM];
__device__ float g_bqkv[3 * DIM];
__device__ int g_vidx[BS * SEQ];
__device__ int g_pidx[BS * SEQ];
__device__ int g_nvalid[BS];

// ---------------------------------------------------------------------------
// Mask compaction: one block per batch, prefix sum over 2048 mask ints.
// ---------------------------------------------------------------------------
__global__ __launch_bounds__(256) void compact_mask(const int* __restrict__ mask)
{
    __shared__ int part[256];
    const int b = blockIdx.x, t = threadIdx.x;
    int loc[8], sum = 0;
#pragma unroll
    for (int i = 0; i < 8; i++) {
        loc[i] = (mask[b * SEQ + t * 8 + i] != 0) ? 1 : 0;
        sum += loc[i];
    }
    part[t] = sum;
    __syncthreads();
    for (int off = 1; off < 256; off <<= 1) {
        int v = (t >= off) ? part[t - off] : 0;
        __syncthreads();
        part[t] += v;
        __syncthreads();
    }
    int pre = part[t] - sum;
#pragma unroll
    for (int i = 0; i < 8; i++) {
        int s = t * 8 + i;
        g_pidx[b * SEQ + s] = pre;
        if (loc[i]) { g_vidx[b * SEQ + pre] = s; pre++; }
    }
    if (t == 255) g_nvalid[b] = part[255];
}

// ---------------------------------------------------------------------------
// Gather raw q/k/v rows into compacted single-fp16 planes (zero pad).
// ---------------------------------------------------------------------------
__global__ __launch_bounds__(256) void gather_qkv(
    const float* __restrict__ q, const float* __restrict__ k,
    const float* __restrict__ v)
{
    const int b = blockIdx.y, i = blockIdx.x, t = threadIdx.x;
    const int nv = g_nvalid[b];
    const size_t dst = ((size_t)b * SEQ + i) * DIM + t * 4;
    if (i < nv) {
        const int s = g_vidx[b * SEQ + i];
        const size_t src = ((size_t)b * SEQ + s) * DIM + t * 4;
        float4 a = *(const float4*)(q + src);
        float4 c = *(const float4*)(k + src);
        float4 d = *(const float4*)(v + src);
        *(__half2*)(g_Qr + dst)     = __floats2half2_rn(a.x, a.y);
        *(__half2*)(g_Qr + dst + 2) = __floats2half2_rn(a.z, a.w);
        *(__half2*)(g_Kr + dst)     = __floats2half2_rn(c.x, c.y);
        *(__half2*)(g_Kr + dst + 2) = __floats2half2_rn(c.z, c.w);
        *(__half2*)(g_Vr + dst)     = __floats2half2_rn(d.x, d.y);
        *(__half2*)(g_Vr + dst + 2) = __floats2half2_rn(d.z, d.w);
    } else {
        const __half2 z = __floats2half2_rn(0.f, 0.f);
        *(__half2*)(g_Qr + dst) = z; *(__half2*)(g_Qr + dst + 2) = z;
        *(__half2*)(g_Kr + dst) = z; *(__half2*)(g_Kr + dst + 2) = z;
        *(__half2*)(g_Vr + dst) = z; *(__half2*)(g_Vr + dst + 2) = z;
    }
}

// ---------------------------------------------------------------------------
// Convert weights to fp16 (Wq pre-scaled 0.125) + bias prep (merged kernel).
// ---------------------------------------------------------------------------
__global__ __launch_bounds__(256) void prep_weights(
    const float* __restrict__ Wq, const float* __restrict__ Wk,
    const float* __restrict__ Wv, const float* __restrict__ Wo,
    const float* __restrict__ bq, const float* __restrict__ bk,
    const float* __restrict__ bv)
{
    const int mat = blockIdx.y;
    const int bx = blockIdx.x;
    const int t = threadIdx.x;
    const float* src = (mat == 0) ? Wq : (mat == 1) ? Wk : (mat == 2) ? Wv : Wo;
    const float sc = (mat == 0) ? 0.125f : 1.0f;
    const size_t idx = (size_t)bx * 1024 + t * 4;
    float4 a = *(const float4*)(src + idx);
    const size_t dst = (size_t)mat * DIM * DIM + idx;
    *(__half2*)(g_W + dst)     = __floats2half2_rn(a.x * sc, a.y * sc);
    *(__half2*)(g_W + dst + 2) = __floats2half2_rn(a.z * sc, a.w * sc);
    // bias prep piggybacked on the first three x-blocks of mat 0
    if (mat == 0 && bx < 3) {
        const float* bsrc = (bx == 0) ? bq : (bx == 1) ? bk : bv;
        const float sc2 = (bx == 0) ? 0.125f : 1.0f;
#pragma unroll
        for (int j = 0; j < 4; j++) {
            const int i = t * 4 + j;
            g_bqkv[bx * 1024 + i] = bsrc[i] * sc2;
        }
    }
}

// ---------------------------------------------------------------------------
// Fill masked output rows with bias bo.
// ---------------------------------------------------------------------------
__global__ __launch_bounds__(256) void fill_masked(
    const int* __restrict__ mask, const float* __restrict__ bo,
    float* __restrict__ out)
{
    const int b = blockIdx.y, s = blockIdx.x, t = threadIdx.x;
    if (mask[b * SEQ + s] != 0) return;
    const size_t dst = ((size_t)b * SEQ + s) * DIM;
    ((float4*)(out + dst))[t] = ((const float4*)bo)[t];
}

// ---------------------------------------------------------------------------
// GEMM core (NT): C[128,128] = A[128,K] @ W[128,K]^T + bias, fp16.
// BK=32, cp.async 3-STAGE RING with ONE sync per k-iter, 2 CTAs/SM.
// 256 threads, 8 warps (2x4), warp tile 64x32.
// MODE 0: fp16 plane out (QKV). MODE 1: fp32 scatter-to-output via vidx (O).
// ---------------------------------------------------------------------------
#define GBM 128
#define GBN 128
#define GBK 32
#define GSTR 40                  // smem row stride in halfs (80B)
#define PLANE_B 10240            // 128*40*2 bytes
#define STAGE_B (2 * PLANE_B)    // A, W = 20480
#define GEMM_SMEM 67584          // max(3*STAGE_B=61440, epilogue 128*132*4)

template<int MODE>
__device__ __forceinline__ void gemm_core(
    const __half* __restrict__ Ap, const __half* __restrict__ Bp,
    const float* __restrict__ biasp,
    __half* __restrict__ Hp,
    float* __restrict__ outb, const int* __restrict__ vl, int nrem)
{
    extern __shared__ char smem[];
    const uint32_t sb = (uint32_t)__cvta_generic_to_shared(smem);
    const int tid = threadIdx.x;
    const int w = tid >> 5, wr = w >> 2, wc = w & 3;

    const __half* gsrc[2] = { Ap, Bp };

    wmma::fragment<wmma::accumulator, 16, 16, 16, float> acc[4][2];
#pragma unroll
    for (int i = 0; i < 4; i++)
#pragma unroll
        for (int j = 0; j < 2; j++) wmma::fill_fragment(acc[i][j], 0.f);

    // 1024 16B chunks per stage (2 planes x 512), 4 per thread
    auto issue = [&](int t, int buf) {
#pragma unroll
        for (int p = 0; p < 4; p++) {
            const int idx = p * 256 + tid;            // 0..1023
            const int plane = idx >> 9;
            const int c = idx & 511;
            const int row = c >> 2, col = (c & 3) * 8;
            const void* src = gsrc[plane] + (size_t)row * DIM + t * GBK + col;
            const uint32_t dst = sb + buf * STAGE_B + plane * PLANE_B
                               + (row * GSTR + col) * 2;
            asm volatile("cp.async.cg.shared.global [%0], [%1], 16;\n"
                         :: "r"(dst), "l"(src));
        }
        asm volatile("cp.async.commit_group;\n");
    };

    auto compute = [&](int buf) {
        const __half* As = (const __half*)(smem + buf * STAGE_B);
        const __half* Bs = As + PLANE_B / 2;
#pragma unroll
        for (int kk = 0; kk < 2; kk++) {
            wmma::fragment<wmma::matrix_a, 16, 16, 16, __half, wmma::row_major> af[4];
#pragma unroll
            for (int i = 0; i < 4; i++)
                wmma::load_matrix_sync(af[i], As + (wr * 64 + i * 16) * GSTR + kk * 16, GSTR);
#pragma unroll
            for (int j = 0; j < 2; j++) {
                wmma::fragment<wmma::matrix_b, 16, 16, 16, __half, wmma::col_major> bf;
                wmma::load_matrix_sync(bf, Bs + (wc * 32 + j * 16) * GSTR + kk * 16, GSTR);
#pragma unroll
                for (int i = 0; i < 4; i++)
                    wmma::mma_sync(acc[i][j], af[i], bf, acc[i][j]);
            }
        }
    };

    // 3-stage ring, ONE __syncthreads per iter (pattern proven in round 6):
    // issue(t+2) overwrites buf (t-1)%3, whose reader compute(t-1) is sealed
    // by this iteration's sync.
    const int NT = DIM / GBK;   // 32
    issue(0, 0);
    issue(1, 1);
    for (int t = 0; t < NT; t++) {
        if (t + 1 < NT) asm volatile("cp.async.wait_group 1;\n");
        else            asm volatile("cp.async.wait_group 0;\n");
        __syncthreads();                    // stage t visible; compute(t-1) sealed
        compute(t % 3);
        if (t + 2 < NT) issue(t + 2, (t + 2) % 3);
    }
    __syncthreads();

    // epilogue: fp32 staging + bias
    float* Cs = (float*)smem;   // 128 x 132
#pragma unroll
    for (int i = 0; i < 4; i++)
#pragma unroll
        for (int j = 0; j < 2; j++)
            wmma::store_matrix_sync(Cs + (wr * 64 + i * 16) * 132 + wc * 32 + j * 16,
                                    acc[i][j], 132, wmma::mem_row_major);
    __syncthreads();

#pragma unroll
    for (int it = 0; it < 16; it++) {
        const int f = tid + it * 256;
        const int r = f >> 5, c = (f & 31) * 4;
        float4 vv = *(const float4*)(Cs + r * 132 + c);
        const float4 bb = *(const float4*)(biasp + c);
        const float x0 = vv.x + bb.x;
        const float x1 = vv.y + bb.y;
        const float x2 = vv.z + bb.z;
        const float x3 = vv.w + bb.w;
        if (MODE == 0) {
            const size_t off = (size_t)r * DIM + c;
            *(__half2*)(Hp + off)     = __floats2half2_rn(x0, x1);
            *(__half2*)(Hp + off + 2) = __floats2half2_rn(x2, x3);
        } else {
            if (r < nrem) {   // valid compacted row -> scatter to original slot
                const int orow = vl[r];
                *(float4*)(outb + (size_t)orow * DIM + c) =
                    make_float4(x0, x1, x2, x3);
            }
        }
    }
}

// fused QKV projection: grid (3072/128, MTOT/128)
__global__ __launch_bounds__(256, 2) void gemm_qkv()
{
    const int m0 = blockIdx.y * GBM;
    const int n0 = blockIdx.x * GBN;
    {
        const int nv = g_nvalid[m0 >> 11];
        const int nvpad = (nv + GBM - 1) & ~(GBM - 1);
        if ((m0 & (SEQ - 1)) >= nvpad) return;
    }
    const int sec = n0 >> 10;          // 0=Q, 1=K, 2=V
    const int nc = n0 & 1023;
    const __half* Ap = (sec == 0) ? g_Qr : (sec == 1) ? g_Kr : g_Vr;
    __half* Hp = ((sec == 0) ? g_Qp : (sec == 1) ? g_Kp : g_Vp)
                 + (size_t)m0 * DIM + nc;
    gemm_core<0>(Ap + (size_t)m0 * DIM, g_W + (size_t)n0 * DIM,
                 g_bqkv + n0, Hp, nullptr, nullptr, 0);
}

// output projection with scattered epilogue: grid (1024/128, MTOT/128)
__global__ __launch_bounds__(256, 2) void gemm_o(const float* __restrict__ bo,
                                                 float* __restrict__ out)
{
    const int m0 = blockIdx.y * GBM;
    const int n0 = blockIdx.x * GBN;
    const int b  = m0 >> 11;
    const int ml = m0 & (SEQ - 1);
    const int nv = g_nvalid[b];
    {
        const int nvpad = (nv + GBM - 1) & ~(GBM - 1);
        if (ml >= nvpad) return;
    }
    gemm_core<1>(g_Cc + (size_t)m0 * DIM,
                 g_W + (size_t)3 * DIM * DIM + (size_t)n0 * DIM,
                 bo + n0, nullptr,
                 out + (size_t)b * SEQ * DIM + n0,
                 g_vidx + b * SEQ + ml, nv - ml);
}

// ---------------------------------------------------------------------------
// Flash attention, SOFTWARE-PIPELINED (kept from round 15 — the component
// that helped): S-MMA shifted one iteration ahead, 2 syncs/iter, K/V double-
// buffered, one cp.async group {V[i], K[i+1]} per iter.
// smem (bytes): Q 0 (18432) | K s: 18432+s*9216 | V s: 36864+s*9216
//               S f32 55296 (128x72) | P fp16 92160 ; total 110592 -> 2 CTAs/SM
// ---------------------------------------------------------------------------
#define ABQ 128
#define ABK 64
#define APB 72
#define APS 72
#define FQOF 0
#define FKOF(s) (18432 + (s) * 9216)
#define FVOF(s) (36864 + (s) * 9216)
#define FSOF 55296
#define FPOF 92160
#define FA_SMEM 110592

__global__ __launch_bounds__(256, 2) void flash_attn_fp16()
{
    const int b = blockIdx.z, h = blockIdx.y;
    const int nk = g_nvalid[b];
    const int q0 = blockIdx.x * ABQ;
    if (q0 >= nk) return;

    extern __shared__ char smem[];
    const uint32_t sb = (uint32_t)__cvta_generic_to_shared(smem);
    __half* Qs  = (__half*)(smem + FQOF);
    float*  Ssm = (float*)(smem + FSOF);
    __half* Ps  = (__half*)(smem + FPOF);

    const int tid = threadIdx.x;
    const int w = tid >> 5;
    const int niter = (nk + ABK - 1) / ABK;

    auto issueK = [&](int i) {   // K[i] -> Kbuf[i&1]
        const size_t rb = ((size_t)b * SEQ + i * ABK) * DIM + h * DK;
#pragma unroll
        for (int p = 0; p < 2; p++) {
            const int c = p * 256 + tid;
            const int row = c >> 3, col = (c & 7) * 8;
            const void* src = g_Kp + rb + (size_t)row * DIM + col;
            const uint32_t dst = sb + FKOF(i & 1) + (row * APB + col) * 2;
            asm volatile("cp.async.cg.shared.global [%0], [%1], 16;\n"
                         :: "r"(dst), "l"(src));
        }
    };
    auto issueV = [&](int i) {   // V[i] -> Vbuf[i&1]
        const size_t rb = ((size_t)b * SEQ + i * ABK) * DIM + h * DK;
#pragma unroll
        for (int p = 0; p < 2; p++) {
            const int c = p * 256 + tid;
            const int row = c >> 3, col = (c & 7) * 8;
            const void* src = g_Vp + rb + (size_t)row * DIM + col;
            const uint32_t dst = sb + FVOF(i & 1) + (row * APB + col) * 2;
            asm volatile("cp.async.cg.shared.global [%0], [%1], 16;\n"
                         :: "r"(dst), "l"(src));
        }
    };
    auto issueKV = [&](int i) {  // group {V[i], K[i+1]}; always commits
        if (i < niter) issueV(i);
        if (i + 1 < niter) issueK(i + 1);
        asm volatile("cp.async.commit_group;\n");
    };

    auto smma = [&](int i) {     // S = Q @ K[i]^T -> Ssm
        const __half* Ks = (const __half*)(smem + FKOF(i & 1));
        wmma::fragment<wmma::accumulator, 16, 16, 16, float> acc[4];
#pragma unroll
        for (int j = 0; j < 4; j++) wmma::fill_fragment(acc[j], 0.f);
#pragma unroll
        for (int kk = 0; kk < 4; kk++) {
            wmma::fragment<wmma::matrix_a, 16, 16, 16, __half, wmma::row_major> af;
            wmma::load_matrix_sync(af, Qs + (16 * w) * APB + kk * 16, APB);
#pragma unroll
            for (int j = 0; j < 4; j++) {
                wmma::fragment<wmma::matrix_b, 16, 16, 16, __half, wmma::col_major> bf;
                wmma::load_matrix_sync(bf, Ks + (j * 16) * APB + kk * 16, APB);
                wmma::mma_sync(acc[j], af, bf, acc[j]);
            }
        }
#pragma unroll
        for (int j = 0; j < 4; j++)
            wmma::store_matrix_sync(Ssm + (16 * w) * APS + j * 16, acc[j], APS,
                                    wmma::mem_row_major);
    };

    // ---- prologue ----
    issueK(0);
    asm volatile("cp.async.commit_group;\n");     // G0 = {K0}
    {   // Q tile: 128 rows x 64 halfs
        const size_t rb = ((size_t)b * SEQ + q0) * DIM + h * DK;
        for (int f = tid; f < 1024; f += 256) {
            const int r = f >> 3, c = (f & 7) * 8;
            *(uint4*)(Qs + r * APB + c) = *(const uint4*)(g_Qp + rb + (size_t)r * DIM + c);
        }
    }
    issueKV(0);                                   // G1 = {V0, K1?}
    asm volatile("cp.async.wait_group 1;\n");     // K0 arrived (G1 pending)
    __syncthreads();                              // Q + K0 visible
    smma(0);
    __syncthreads();                              // S0 visible

    wmma::fragment<wmma::accumulator, 16, 16, 16, float> accO[4];
#pragma unroll
    for (int j = 0; j < 4; j++) wmma::fill_fragment(accO[j], 0.f);

    const int row = tid >> 1;
    const int cbase = (tid & 1) * 32;
    float lrun = 0.f;

    // ---- pipelined mainloop ----
    for (int i = 0; i < niter; i++) {
        const int kt = i * ABK;

        // softmax on S[i]: p = exp(s), pad -> 0 exactly; write P[i]
        float lsum = 0.f;
#pragma unroll
        for (int c = 0; c < 32; c += 2) {
            float s0 = Ssm[row * APS + cbase + c];
            float s1 = Ssm[row * APS + cbase + c + 1];
            if (kt + cbase + c >= nk)     s0 = FNEG;
            if (kt + cbase + c + 1 >= nk) s1 = FNEG;
            const float p0 = __expf(s0), p1 = __expf(s1);
            lsum += p0 + p1;
            *(__half2*)(Ps + row * APB + cbase + c) = __floats2half2_rn(p0, p1);
        }
        lrun += lsum + __shfl_xor_sync(0xffffffffu, lsum, 1);

        asm volatile("cp.async.wait_group 0;\n"); // V[i] (+K[i+1]) arrived
        __syncthreads();                          // P[i] visible, S free, K/V visible

        if (i + 1 < niter) issueKV(i + 1);        // launch {V[i+1], K[i+2]?}

        // packed MMA phase: S[i+1] and PV[i] issue together
        if (i + 1 < niter) smma(i + 1);
        {
            const __half* Vs = (const __half*)(smem + FVOF(i & 1));
#pragma unroll
            for (int kk = 0; kk < 4; kk++) {
                wmma::fragment<wmma::matrix_a, 16, 16, 16, __half, wmma::row_major> pf;
                wmma::load_matrix_sync(pf, Ps + (16 * w) * APB + kk * 16, APB);
#pragma unroll
                for (int j = 0; j < 4; j++) {
                    wmma::fragment<wmma::matrix_b, 16, 16, 16, __half, wmma::row_major> vf;
                    wmma::load_matrix_sync(vf, Vs + (kk * 16) * APB + j * 16, APB);
                    wmma::mma_sync(accO[j], pf, vf, accO[j]);
                }
            }
        }
        __syncthreads();                          // S[i+1] visible; K/V/P reads sealed
    }

    // ---- epilogue: stage O through S region, normalize, emit fp16 context ----
    float* Osm = (float*)(smem + FSOF);
#pragma unroll
    for (int j = 0; j < 4; j++)
        wmma::store_matrix_sync(Osm + (16 * w) * 68 + j * 16, accO[j], 68,
                                wmma::mem_row_major);
    __syncthreads();

    const float inv = (lrun > 0.f) ? (1.f / lrun) : 0.f;
    const size_t ob = ((size_t)b * SEQ + q0 + row) * DIM + h * DK + cbase;
#pragma unroll
    for (int c = 0; c < 32; c += 2) {
        const float a = Osm[row * 68 + cbase + c] * inv;
        const float d = Osm[row * 68 + cbase + c + 1] * inv;
        *(__half2*)(g_Cc + ob + c) = __floats2half2_rn(a, d);
    }
}

// ---------------------------------------------------------------------------
// launch
// ---------------------------------------------------------------------------
extern "C" void kernel_launch(void* const* d_in, const int* in_sizes, int n_in,
                              void* d_out, int out_size)
{
    const float* q    = (const float*)d_in[0];
    const float* k    = (const float*)d_in[1];
    const float* v    = (const float*)d_in[2];
    const int*   mask = (const int*)  d_in[3];
    const float* Wq   = (const float*)d_in[4];
    const float* bq   = (const float*)d_in[5];
    const float* Wk   = (const float*)d_in[6];
    const float* bk   = (const float*)d_in[7];
    const float* Wv   = (const float*)d_in[8];
    const float* bv   = (const float*)d_in[9];
    const float* Wo   = (const float*)d_in[10];
    const float* bo   = (const float*)d_in[11];
    float* out = (float*)d_out;

    cudaFuncSetAttribute(gemm_qkv, cudaFuncAttributeMaxDynamicSharedMemorySize, GEMM_SMEM);
    cudaFuncSetAttribute(gemm_o,   cudaFuncAttributeMaxDynamicSharedMemorySize, GEMM_SMEM);
    cudaFuncSetAttribute(flash_attn_fp16, cudaFuncAttributeMaxDynamicSharedMemorySize, FA_SMEM);

    // 1. compact mask, build indices
    compact_mask<<<BS, 256>>>(mask);

    // 2. gather raw q/k/v (fp16); convert weights + bias (merged)
    gather_qkv<<<dim3(SEQ, BS), 256>>>(q, k, v);
    prep_weights<<<dim3(1024, 4), 256>>>(Wq, Wk, Wv, Wo, bq, bk, bv);

    // 3. fused QKV projection (fp16; 3-stage ring; scale folded into Wq/bq)
    gemm_qkv<<<dim3(3 * DIM / GBN, MTOT / GBM), 256, GEMM_SMEM>>>();

    // 4. flash attention (software-pipelined, single-pass fp16)
    flash_attn_fp16<<<dim3(SEQ / ABQ, NH, BS), 256, FA_SMEM>>>();

    // 5. output projection, epilogue scatters valid rows directly to out
    gemm_o<<<dim3(DIM / GBN, MTOT / GBM), 256, GEMM_SMEM>>>(bo, out);

    // 6. masked rows = bo
    fill_masked<<<dim3(SEQ, BS), 256>>>(mask, bo, out);
}